// round 8
// baseline (speedup 1.0000x reference)
#include <cuda_runtime.h>
#include <math.h>

#define W   512
#define B   32
#define C   3
#define LIM 0.03125f                     // PIX_W * EPS = (2/512)*8
#define DEF_OFF_F (1.0f + 2.0f/511.0f)   // (2 + 4/511)/2
#define FULL 0xffffffffu

// ---------------- scratch (static device arrays; no runtime allocs) --------
__device__ float d_px[(size_t)B * W * W];         // sample x coord in pixels

// ---------------- gaussian weights: computed per block (double, = numpy) ---
__device__ __forceinline__ void gweights(float& w0, float& w1, float& w2) {
    double sigma = 5.0 * 0.15 + 0.35;             // 1.1
    double p0 = exp(-0.5 * (2.0 / sigma) * (2.0 / sigma));
    double p1 = exp(-0.5 * (1.0 / sigma) * (1.0 / sigma));
    double s = 2.0 * p0 + 2.0 * p1 + 1.0;
    w0 = (float)(p0 / s);
    w1 = (float)(p1 / s);
    w2 = (float)(1.0 / s);
}

__device__ __forceinline__ int refl(int i) {
    return i < 0 ? -i : (i >= W ? 2 * W - 2 - i : i);
}

// ==== x-channel: fused blur(ch0) + diff->relu->row scan, 8 rows/block =======
#define RROWS 8
__global__ void k_rowscan(const float* __restrict__ pg) {
    __shared__ float ssrc[RROWS + 4][W];   // 24KB
    __shared__ float svb[RROWS][W];        // 16KB
    int b = blockIdx.y;
    int y0 = blockIdx.x * RROWS;
    int tid = threadIdx.x;                 // 256 threads = 8 warps
    const float* src = pg + (size_t)(b * 2) * W * W;   // channel 0

    for (int i = tid; i < (RROWS + 4) * W; i += 256) {
        int r = i >> 9, x = i & 511;
        ssrc[r][x] = src[(size_t)refl(y0 + r - 2) * W + x];
    }
    __syncthreads();

    float w0, w1, w2;
    gweights(w0, w1, w2);
    int warp = tid >> 5, lane = tid & 31;
    int y = y0 + warp;

    #pragma unroll
    for (int k = 0; k < 16; k++) {
        int x = k * 32 + lane;
        svb[warp][x] = w0 * (ssrc[warp][x] + ssrc[warp + 4][x])
                     + w1 * (ssrc[warp + 1][x] + ssrc[warp + 3][x])
                     + w2 * ssrc[warp + 2][x];
    }
    __syncwarp();

    float last31 = 0.f;
    float run = 0.f;
    float* pxo = d_px + ((size_t)b * W + y) * W;
    #pragma unroll
    for (int k = 0; k < 16; k++) {
        int x = k * 32 + lane;
        float bl = w0 * (svb[warp][refl(x - 2)] + svb[warp][refl(x + 2)])
                 + w1 * (svb[warp][refl(x - 1)] + svb[warp][refl(x + 1)])
                 + w2 * svb[warp][x];
        float iden = (2.0f * x - (float)(W - 1)) * (1.0f / (W - 1));
        float s = bl + iden + DEF_OFF_F;
        float sprev = __shfl_up_sync(FULL, s, 1);
        if (lane == 0) sprev = last31;
        float a = fmaxf(s - sprev, 0.f);
        last31 = __shfl_sync(FULL, s, 31);

        float v = a;
        #pragma unroll
        for (int o = 1; o < 32; o <<= 1) {
            float n = __shfl_up_sync(FULL, v, o);
            if (lane >= o) v += n;
        }
        float sx2 = run + v;
        run += __shfl_sync(FULL, v, 31);

        float pgv = sx2 - DEF_OFF_F - iden;
        pgv = fminf(fmaxf(pgv, -LIM), LIM);
        float gx = fminf(fmaxf(pgv + iden, -1.f), 1.f);
        pxo[x] = (gx + 1.f) * 0.5f * (float)(W - 1);
    }
}

// ==== y-channel: fused blur(ch1) + column scan + bilinear sampling ==========
// block (32,16): 32 columns x 512 rows. After the scan, each thread holds the
// final fy for its 32 pixels in registers and samples the image directly.
#define SEG 32
#define NSEG (W / SEG)
__global__ void k_colsample(const float* __restrict__ pg,
                            const float* __restrict__ img,
                            float* __restrict__ out) {
    extern __shared__ float hb[];          // [W][32] = 64KB
    __shared__ float segsum[NSEG][33];
    int tx = threadIdx.x;                  // 0..31 column in tile
    int ty = threadIdx.y;                  // 0..15 segment
    int x = blockIdx.x * 32 + tx;
    int b = blockIdx.y;
    const float* src = pg + (size_t)(b * 2 + 1) * W * W;   // channel 1
    float w0, w1, w2;
    gweights(w0, w1, w2);

    int xm2 = refl(x - 2), xm1 = refl(x - 1), xp1 = refl(x + 1), xp2 = refl(x + 2);

    // phase 1: horizontal blur for this column, rows ty*32 .. ty*32+31
    int y0 = ty * SEG;
    #pragma unroll 4
    for (int r = 0; r < SEG; r++) {
        const float* row = src + (size_t)(y0 + r) * W;
        hb[(y0 + r) * 32 + tx] =
            w0 * (__ldg(row + xm2) + __ldg(row + xp2))
          + w1 * (__ldg(row + xm1) + __ldg(row + xp1))
          + w2 * __ldg(row + x);
    }
    __syncthreads();

    // phase 2: serial scan with rolling vertical-blur window
    float h0 = hb[refl(y0 - 2) * 32 + tx];
    float h1 = hb[refl(y0 - 1) * 32 + tx];
    float h2 = hb[y0 * 32 + tx];
    float h3 = hb[(y0 + 1) * 32 + tx];
    float h4 = hb[refl(y0 + 2) * 32 + tx];

    float prev = 0.f;
    if (ty > 0) {   // s at row y0-1
        float g0 = hb[refl(y0 - 3) * 32 + tx];
        float vbp = w0 * (g0 + h3) + w1 * (h0 + h2) + w2 * h1;
        float idenp = (2.0f * (y0 - 1) - (float)(W - 1)) * (1.0f / (W - 1));
        prev = vbp + idenp + DEF_OFF_F;
    }

    float vals[SEG];
    float run = 0.f;
    #pragma unroll
    for (int r = 0; r < SEG; r++) {
        int y = y0 + r;
        float vb = w0 * (h0 + h4) + w1 * (h1 + h3) + w2 * h2;
        float iden = (2.0f * y - (float)(W - 1)) * (1.0f / (W - 1));
        float s = vb + iden + DEF_OFF_F;
        float a = fmaxf(s - prev, 0.f);
        prev = s;
        run += a;
        vals[r] = run;
        h0 = h1; h1 = h2; h2 = h3; h3 = h4;
        h4 = hb[refl(y + 3) * 32 + tx];
    }
    segsum[ty][tx] = run;
    __syncthreads();

    if (ty == 0) {
        float off = 0.f;
        #pragma unroll
        for (int k = 0; k < NSEG; k++) {
            float t = segsum[k][tx];
            segsum[k][tx] = off;
            off += t;
        }
    }
    __syncthreads();
    float offset = segsum[ty][tx];

    // phase 3: finalize fy per row and sample the image (fx from d_px)
    const float* ib = img + (size_t)b * C * W * W;
    const float* pxc = d_px + (size_t)b * W * W + x;
    float* ob = out + (size_t)b * C * W * W + x;

    #pragma unroll 4
    for (int r = 0; r < SEG; r++) {
        int y = y0 + r;
        float iden = (2.0f * y - (float)(W - 1)) * (1.0f / (W - 1));
        float sy2 = vals[r] + offset;
        float pgv = sy2 - DEF_OFF_F - iden;
        pgv = fminf(fmaxf(pgv, -LIM), LIM);
        float gy = fminf(fmaxf(pgv + iden, -1.f), 1.f);
        float fy = (gy + 1.f) * 0.5f * (float)(W - 1);
        float fx = __ldg(pxc + (size_t)y * W);

        float x0f = floorf(fx), y0f = floorf(fy);
        int x0 = (int)x0f, yy0 = (int)y0f;
        int x1 = x0 + 1, yy1 = yy0 + 1;
        float wx1 = fx - x0f, wx0 = 1.f - wx1;
        float wy1 = fy - y0f, wy0 = 1.f - wy1;

        bool vx0 = (x0 >= 0) & (x0 < W);
        bool vx1 = (x1 >= 0) & (x1 < W);
        bool vy0 = (yy0 >= 0) & (yy0 < W);
        bool vy1 = (yy1 >= 0) & (yy1 < W);

        int x0c = min(max(x0, 0), W - 1), x1c = min(max(x1, 0), W - 1);
        int y0c = min(max(yy0, 0), W - 1), y1c = min(max(yy1, 0), W - 1);

        float w00 = wx0 * wy0 * (float)(vx0 && vy0);
        float w10 = wx1 * wy0 * (float)(vx1 && vy0);
        float w01 = wx0 * wy1 * (float)(vx0 && vy1);
        float w11 = wx1 * wy1 * (float)(vx1 && vy1);

        size_t o00 = (size_t)y0c * W + x0c, o10 = (size_t)y0c * W + x1c;
        size_t o01 = (size_t)y1c * W + x0c, o11 = (size_t)y1c * W + x1c;
        #pragma unroll
        for (int c = 0; c < C; c++) {
            const float* ic = ib + (size_t)c * W * W;
            float v = w00 * __ldg(ic + o00) + w10 * __ldg(ic + o10)
                    + w01 * __ldg(ic + o01) + w11 * __ldg(ic + o11);
            ob[((size_t)c * W + y) * W] = v;
        }
    }
}

// ---------------- launch -----------------------------------------------------
extern "C" void kernel_launch(void* const* d_in, const int* in_sizes, int n_in,
                              void* d_out, int out_size) {
    const float* image = (const float*)d_in[0];
    const float* prim  = (const float*)d_in[1];
    if (in_sizes[0] == B * 2 * W * W) {     // defensive input identification
        prim  = (const float*)d_in[0];
        image = (const float*)d_in[1];
    }

    static bool attr_done = false;
    if (!attr_done) {
        cudaFuncSetAttribute(k_colsample,
                             cudaFuncAttributeMaxDynamicSharedMemorySize,
                             W * 32 * (int)sizeof(float));
        attr_done = true;
    }

    dim3 rg(W / RROWS, B);
    k_rowscan<<<rg, 256>>>(prim);

    dim3 cb(32, NSEG);
    dim3 cg(W / 32, B);
    k_colsample<<<cg, cb, W * 32 * sizeof(float)>>>(prim, image, (float*)d_out);
}

// round 9
// speedup vs baseline: 1.4138x; 1.4138x over previous
#include <cuda_runtime.h>
#include <math.h>

#define W   512
#define B   32
#define C   3
#define LIM 0.03125f                     // PIX_W * EPS = (2/512)*8
#define DEF_OFF_F (1.0f + 2.0f/511.0f)   // (2 + 4/511)/2
#define FULL 0xffffffffu

// ---------------- scratch (static device arrays; no runtime allocs) --------
__device__ float d_px[(size_t)B * W * W];         // sample x coord in pixels
__device__ float d_py[(size_t)B * W * W];         // sample y coord in pixels

// ---------------- gaussian weights: computed per thread (double, = numpy) --
__device__ __forceinline__ void gweights(float& w0, float& w1, float& w2) {
    double sigma = 5.0 * 0.15 + 0.35;             // 1.1
    double p0 = exp(-0.5 * (2.0 / sigma) * (2.0 / sigma));
    double p1 = exp(-0.5 * (1.0 / sigma) * (1.0 / sigma));
    double s = 2.0 * p0 + 2.0 * p1 + 1.0;
    w0 = (float)(p0 / s);
    w1 = (float)(p1 / s);
    w2 = (float)(1.0 / s);
}

__device__ __forceinline__ int refl(int i) {
    return i < 0 ? -i : (i >= W ? 2 * W - 2 - i : i);
}

// ==== x-channel: fused blur(ch0) + diff->relu->row scan, 8 rows/block =======
#define RROWS 8
__global__ void k_rowscan(const float* __restrict__ pg) {
    __shared__ float ssrc[RROWS + 4][W];   // 24KB
    __shared__ float svb[RROWS][W];        // 16KB
    int b = blockIdx.y;
    int y0 = blockIdx.x * RROWS;
    int tid = threadIdx.x;                 // 256 threads = 8 warps
    const float* src = pg + (size_t)(b * 2) * W * W;   // channel 0

    for (int i = tid; i < (RROWS + 4) * W; i += 256) {
        int r = i >> 9, x = i & 511;
        ssrc[r][x] = src[(size_t)refl(y0 + r - 2) * W + x];
    }
    __syncthreads();

    float w0, w1, w2;
    gweights(w0, w1, w2);
    int warp = tid >> 5, lane = tid & 31;
    int y = y0 + warp;

    #pragma unroll
    for (int k = 0; k < 16; k++) {
        int x = k * 32 + lane;
        svb[warp][x] = w0 * (ssrc[warp][x] + ssrc[warp + 4][x])
                     + w1 * (ssrc[warp + 1][x] + ssrc[warp + 3][x])
                     + w2 * ssrc[warp + 2][x];
    }
    __syncwarp();

    float last31 = 0.f;
    float run = 0.f;
    float* pxo = d_px + ((size_t)b * W + y) * W;
    #pragma unroll
    for (int k = 0; k < 16; k++) {
        int x = k * 32 + lane;
        float bl = w0 * (svb[warp][refl(x - 2)] + svb[warp][refl(x + 2)])
                 + w1 * (svb[warp][refl(x - 1)] + svb[warp][refl(x + 1)])
                 + w2 * svb[warp][x];
        float iden = (2.0f * x - (float)(W - 1)) * (1.0f / (W - 1));
        float s = bl + iden + DEF_OFF_F;
        float sprev = __shfl_up_sync(FULL, s, 1);
        if (lane == 0) sprev = last31;
        float a = fmaxf(s - sprev, 0.f);
        last31 = __shfl_sync(FULL, s, 31);

        float v = a;
        #pragma unroll
        for (int o = 1; o < 32; o <<= 1) {
            float n = __shfl_up_sync(FULL, v, o);
            if (lane >= o) v += n;
        }
        float sx2 = run + v;
        run += __shfl_sync(FULL, v, 31);

        float pgv = sx2 - DEF_OFF_F - iden;
        pgv = fminf(fmaxf(pgv, -LIM), LIM);
        float gx = fminf(fmaxf(pgv + iden, -1.f), 1.f);
        pxo[x] = (gx + 1.f) * 0.5f * (float)(W - 1);
    }
}

// ==== y-channel: fused blur(ch1) + tiled column scan, writes d_py ===========
#define SEG 32
#define NSEG (W / SEG)
__global__ void k_colscan(const float* __restrict__ pg) {
    extern __shared__ float hb[];          // [W][32] = 64KB
    __shared__ float segsum[NSEG][33];
    int tx = threadIdx.x;                  // 0..31 column in tile
    int ty = threadIdx.y;                  // 0..15 segment
    int x = blockIdx.x * 32 + tx;
    int b = blockIdx.y;
    const float* src = pg + (size_t)(b * 2 + 1) * W * W;   // channel 1
    float w0, w1, w2;
    gweights(w0, w1, w2);

    int xm2 = refl(x - 2), xm1 = refl(x - 1), xp1 = refl(x + 1), xp2 = refl(x + 2);

    // phase 1: horizontal blur for this column, rows ty*32 .. ty*32+31
    int y0 = ty * SEG;
    #pragma unroll 4
    for (int r = 0; r < SEG; r++) {
        const float* row = src + (size_t)(y0 + r) * W;
        hb[(y0 + r) * 32 + tx] =
            w0 * (__ldg(row + xm2) + __ldg(row + xp2))
          + w1 * (__ldg(row + xm1) + __ldg(row + xp1))
          + w2 * __ldg(row + x);
    }
    __syncthreads();

    // phase 2: serial scan with rolling vertical-blur window
    float h0 = hb[refl(y0 - 2) * 32 + tx];
    float h1 = hb[refl(y0 - 1) * 32 + tx];
    float h2 = hb[y0 * 32 + tx];
    float h3 = hb[(y0 + 1) * 32 + tx];
    float h4 = hb[refl(y0 + 2) * 32 + tx];

    float prev = 0.f;
    if (ty > 0) {   // s at row y0-1
        float g0 = hb[refl(y0 - 3) * 32 + tx];
        float vbp = w0 * (g0 + h3) + w1 * (h0 + h2) + w2 * h1;
        float idenp = (2.0f * (y0 - 1) - (float)(W - 1)) * (1.0f / (W - 1));
        prev = vbp + idenp + DEF_OFF_F;
    }

    float vals[SEG];
    float run = 0.f;
    #pragma unroll
    for (int r = 0; r < SEG; r++) {
        int y = y0 + r;
        float vb = w0 * (h0 + h4) + w1 * (h1 + h3) + w2 * h2;
        float iden = (2.0f * y - (float)(W - 1)) * (1.0f / (W - 1));
        float s = vb + iden + DEF_OFF_F;
        float a = fmaxf(s - prev, 0.f);
        prev = s;
        run += a;
        vals[r] = run;
        h0 = h1; h1 = h2; h2 = h3; h3 = h4;
        h4 = hb[refl(y + 3) * 32 + tx];
    }
    segsum[ty][tx] = run;
    __syncthreads();

    if (ty == 0) {
        float off = 0.f;
        #pragma unroll
        for (int k = 0; k < NSEG; k++) {
            float t = segsum[k][tx];
            segsum[k][tx] = off;
            off += t;
        }
    }
    __syncthreads();
    float offset = segsum[ty][tx];

    float* py = d_py + (size_t)b * W * W + x;
    #pragma unroll
    for (int r = 0; r < SEG; r++) {
        int y = y0 + r;
        float iden = (2.0f * y - (float)(W - 1)) * (1.0f / (W - 1));
        float sy2 = vals[r] + offset;
        float pgv = sy2 - DEF_OFF_F - iden;
        pgv = fminf(fmaxf(pgv, -LIM), LIM);
        float gy = fminf(fmaxf(pgv + iden, -1.f), 1.f);
        py[(size_t)y * W] = (gy + 1.f) * 0.5f * (float)(W - 1);
    }
}

// ==== bilinear grid sample, 4 pixels / thread ================================
// Grid coords are clipped to [-1,1] upstream => fx,fy in [0,511]:
// no validity predicates needed; only x1/y1 clamp (their weight is 0 there).
__device__ __forceinline__ void samp1(const float* __restrict__ ib,
                                      float fx, float fy,
                                      float& r0, float& r1, float& r2) {
    float x0f = floorf(fx), y0f = floorf(fy);
    int x0 = (int)x0f, y0 = (int)y0f;           // in [0,511]
    int x1 = min(x0 + 1, W - 1), y1 = min(y0 + 1, W - 1);
    float wx1 = fx - x0f, wx0 = 1.f - wx1;
    float wy1 = fy - y0f, wy0 = 1.f - wy1;

    float w00 = wx0 * wy0, w10 = wx1 * wy0;
    float w01 = wx0 * wy1, w11 = wx1 * wy1;

    size_t o00 = (size_t)y0 * W + x0, o10 = (size_t)y0 * W + x1;
    size_t o01 = (size_t)y1 * W + x0, o11 = (size_t)y1 * W + x1;
    r0 = w00 * __ldg(ib + o00) + w10 * __ldg(ib + o10)
       + w01 * __ldg(ib + o01) + w11 * __ldg(ib + o11);
    const float* i1 = ib + (size_t)W * W;
    r1 = w00 * __ldg(i1 + o00) + w10 * __ldg(i1 + o10)
       + w01 * __ldg(i1 + o01) + w11 * __ldg(i1 + o11);
    const float* i2 = ib + (size_t)2 * W * W;
    r2 = w00 * __ldg(i2 + o00) + w10 * __ldg(i2 + o10)
       + w01 * __ldg(i2 + o01) + w11 * __ldg(i2 + o11);
}

__global__ void k_sample(const float* __restrict__ img, float* __restrict__ out) {
    int t = blockIdx.x * blockDim.x + threadIdx.x;     // quad index
    if (t >= B * W * W / 4) return;
    int y = (t >> 7) & 511, b = t >> 16;

    float4 fx4 = ((const float4*)d_px)[t];
    float4 fy4 = ((const float4*)d_py)[t];

    const float* ib = img + (size_t)b * C * W * W;
    float4 c0, c1, c2;
    samp1(ib, fx4.x, fy4.x, c0.x, c1.x, c2.x);
    samp1(ib, fx4.y, fy4.y, c0.y, c1.y, c2.y);
    samp1(ib, fx4.z, fy4.z, c0.z, c1.z, c2.z);
    samp1(ib, fx4.w, fy4.w, c0.w, c1.w, c2.w);

    size_t orow = ((size_t)(b * C) * W + y) * W;
    int xo = (t & 127) * 4;
    *(float4*)(out + orow + xo)                     = c0;
    *(float4*)(out + orow + (size_t)W * W + xo)     = c1;
    *(float4*)(out + orow + (size_t)2 * W * W + xo) = c2;
}

// ---------------- launch -----------------------------------------------------
extern "C" void kernel_launch(void* const* d_in, const int* in_sizes, int n_in,
                              void* d_out, int out_size) {
    const float* image = (const float*)d_in[0];
    const float* prim  = (const float*)d_in[1];
    if (in_sizes[0] == B * 2 * W * W) {     // defensive input identification
        prim  = (const float*)d_in[0];
        image = (const float*)d_in[1];
    }

    static bool attr_done = false;
    if (!attr_done) {
        cudaFuncSetAttribute(k_colscan,
                             cudaFuncAttributeMaxDynamicSharedMemorySize,
                             W * 32 * (int)sizeof(float));
        attr_done = true;
    }

    dim3 rg(W / RROWS, B);
    k_rowscan<<<rg, 256>>>(prim);

    dim3 cb(32, NSEG);
    dim3 cg(W / 32, B);
    k_colscan<<<cg, cb, W * 32 * sizeof(float)>>>(prim);

    k_sample<<<(B * W * W / 4 + 255) / 256, 256>>>(image, (float*)d_out);
}

// round 10
// speedup vs baseline: 2.0258x; 1.4329x over previous
#include <cuda_runtime.h>
#include <math.h>

#define W   512
#define B   32
#define C   3
#define LIM 0.03125f                     // PIX_W * EPS = (2/512)*8
#define DEF_OFF_F (1.0f + 2.0f/511.0f)   // (2 + 4/511)/2
#define FULL 0xffffffffu

// ---------------- scratch (static device arrays; no runtime allocs) --------
__device__ float d_px[(size_t)B * W * W];         // sample x coord in pixels
__device__ float d_py[(size_t)B * W * W];         // sample y coord in pixels

__device__ __forceinline__ int refl(int i) {
    return i < 0 ? -i : (i >= W ? 2 * W - 2 - i : i);
}

// ==== x-channel: fused blur(ch0) + diff->relu->row scan, 8 rows/block =======
#define RROWS 8
__global__ void k_rowscan(const float* __restrict__ pg,
                          float w0, float w1, float w2) {
    __shared__ float ssrc[RROWS + 4][W];   // 24KB
    __shared__ float svb[RROWS][W];        // 16KB
    int b = blockIdx.y;
    int y0 = blockIdx.x * RROWS;
    int tid = threadIdx.x;                 // 256 threads = 8 warps
    const float* src = pg + (size_t)(b * 2) * W * W;   // channel 0

    for (int i = tid; i < (RROWS + 4) * W; i += 256) {
        int r = i >> 9, x = i & 511;
        ssrc[r][x] = src[(size_t)refl(y0 + r - 2) * W + x];
    }
    __syncthreads();

    int warp = tid >> 5, lane = tid & 31;
    int y = y0 + warp;

    #pragma unroll
    for (int k = 0; k < 16; k++) {
        int x = k * 32 + lane;
        svb[warp][x] = w0 * (ssrc[warp][x] + ssrc[warp + 4][x])
                     + w1 * (ssrc[warp + 1][x] + ssrc[warp + 3][x])
                     + w2 * ssrc[warp + 2][x];
    }
    __syncwarp();

    float last31 = 0.f;
    float run = 0.f;
    float* pxo = d_px + ((size_t)b * W + y) * W;
    #pragma unroll
    for (int k = 0; k < 16; k++) {
        int x = k * 32 + lane;
        float bl = w0 * (svb[warp][refl(x - 2)] + svb[warp][refl(x + 2)])
                 + w1 * (svb[warp][refl(x - 1)] + svb[warp][refl(x + 1)])
                 + w2 * svb[warp][x];
        float iden = (2.0f * x - (float)(W - 1)) * (1.0f / (W - 1));
        float s = bl + iden + DEF_OFF_F;
        float sprev = __shfl_up_sync(FULL, s, 1);
        if (lane == 0) sprev = last31;
        float a = fmaxf(s - sprev, 0.f);
        last31 = __shfl_sync(FULL, s, 31);

        float v = a;
        #pragma unroll
        for (int o = 1; o < 32; o <<= 1) {
            float n = __shfl_up_sync(FULL, v, o);
            if (lane >= o) v += n;
        }
        float sx2 = run + v;
        run += __shfl_sync(FULL, v, 31);

        float pgv = sx2 - DEF_OFF_F - iden;
        pgv = fminf(fmaxf(pgv, -LIM), LIM);
        float gx = fminf(fmaxf(pgv + iden, -1.f), 1.f);
        pxo[x] = (gx + 1.f) * 0.5f * (float)(W - 1);
    }
}

// ==== y-channel: fused blur(ch1) + tiled column scan, writes d_py ===========
#define SEG 32
#define NSEG (W / SEG)
__global__ void k_colscan(const float* __restrict__ pg,
                          float w0, float w1, float w2) {
    extern __shared__ float hb[];          // [W][32] = 64KB
    __shared__ float segsum[NSEG][33];
    int tx = threadIdx.x;                  // 0..31 column in tile
    int ty = threadIdx.y;                  // 0..15 segment
    int x = blockIdx.x * 32 + tx;
    int b = blockIdx.y;
    const float* src = pg + (size_t)(b * 2 + 1) * W * W;   // channel 1

    int xm2 = refl(x - 2), xm1 = refl(x - 1), xp1 = refl(x + 1), xp2 = refl(x + 2);

    // phase 1: horizontal blur for this column, rows ty*32 .. ty*32+31
    int y0 = ty * SEG;
    #pragma unroll 4
    for (int r = 0; r < SEG; r++) {
        const float* row = src + (size_t)(y0 + r) * W;
        hb[(y0 + r) * 32 + tx] =
            w0 * (__ldg(row + xm2) + __ldg(row + xp2))
          + w1 * (__ldg(row + xm1) + __ldg(row + xp1))
          + w2 * __ldg(row + x);
    }
    __syncthreads();

    // phase 2: serial scan with rolling vertical-blur window
    float h0 = hb[refl(y0 - 2) * 32 + tx];
    float h1 = hb[refl(y0 - 1) * 32 + tx];
    float h2 = hb[y0 * 32 + tx];
    float h3 = hb[(y0 + 1) * 32 + tx];
    float h4 = hb[refl(y0 + 2) * 32 + tx];

    float prev = 0.f;
    if (ty > 0) {   // s at row y0-1
        float g0 = hb[refl(y0 - 3) * 32 + tx];
        float vbp = w0 * (g0 + h3) + w1 * (h0 + h2) + w2 * h1;
        float idenp = (2.0f * (y0 - 1) - (float)(W - 1)) * (1.0f / (W - 1));
        prev = vbp + idenp + DEF_OFF_F;
    }

    float vals[SEG];
    float run = 0.f;
    #pragma unroll
    for (int r = 0; r < SEG; r++) {
        int y = y0 + r;
        float vb = w0 * (h0 + h4) + w1 * (h1 + h3) + w2 * h2;
        float iden = (2.0f * y - (float)(W - 1)) * (1.0f / (W - 1));
        float s = vb + iden + DEF_OFF_F;
        float a = fmaxf(s - prev, 0.f);
        prev = s;
        run += a;
        vals[r] = run;
        h0 = h1; h1 = h2; h2 = h3; h3 = h4;
        h4 = hb[refl(y + 3) * 32 + tx];
    }
    segsum[ty][tx] = run;
    __syncthreads();

    if (ty == 0) {
        float off = 0.f;
        #pragma unroll
        for (int k = 0; k < NSEG; k++) {
            float t = segsum[k][tx];
            segsum[k][tx] = off;
            off += t;
        }
    }
    __syncthreads();
    float offset = segsum[ty][tx];

    float* py = d_py + (size_t)b * W * W + x;
    #pragma unroll
    for (int r = 0; r < SEG; r++) {
        int y = y0 + r;
        float iden = (2.0f * y - (float)(W - 1)) * (1.0f / (W - 1));
        float sy2 = vals[r] + offset;
        float pgv = sy2 - DEF_OFF_F - iden;
        pgv = fminf(fmaxf(pgv, -LIM), LIM);
        float gy = fminf(fmaxf(pgv + iden, -1.f), 1.f);
        py[(size_t)y * W] = (gy + 1.f) * 0.5f * (float)(W - 1);
    }
}

// ==== bilinear grid sample, 4 pixels / thread ================================
// Grid coords are clipped to [-1,1] upstream => fx,fy in [0,511]:
// no validity predicates needed; only x1/y1 clamp (their weight is 0 there).
__device__ __forceinline__ void samp1(const float* __restrict__ ib,
                                      float fx, float fy,
                                      float& r0, float& r1, float& r2) {
    float x0f = floorf(fx), y0f = floorf(fy);
    int x0 = (int)x0f, y0 = (int)y0f;           // in [0,511]
    int x1 = min(x0 + 1, W - 1), y1 = min(y0 + 1, W - 1);
    float wx1 = fx - x0f, wx0 = 1.f - wx1;
    float wy1 = fy - y0f, wy0 = 1.f - wy1;

    float w00 = wx0 * wy0, w10 = wx1 * wy0;
    float w01 = wx0 * wy1, w11 = wx1 * wy1;

    size_t o00 = (size_t)y0 * W + x0, o10 = (size_t)y0 * W + x1;
    size_t o01 = (size_t)y1 * W + x0, o11 = (size_t)y1 * W + x1;
    r0 = w00 * __ldg(ib + o00) + w10 * __ldg(ib + o10)
       + w01 * __ldg(ib + o01) + w11 * __ldg(ib + o11);
    const float* i1 = ib + (size_t)W * W;
    r1 = w00 * __ldg(i1 + o00) + w10 * __ldg(i1 + o10)
       + w01 * __ldg(i1 + o01) + w11 * __ldg(i1 + o11);
    const float* i2 = ib + (size_t)2 * W * W;
    r2 = w00 * __ldg(i2 + o00) + w10 * __ldg(i2 + o10)
       + w01 * __ldg(i2 + o01) + w11 * __ldg(i2 + o11);
}

__global__ void k_sample(const float* __restrict__ img, float* __restrict__ out) {
    int t = blockIdx.x * blockDim.x + threadIdx.x;     // quad index
    if (t >= B * W * W / 4) return;
    int y = (t >> 7) & 511, b = t >> 16;

    float4 fx4 = ((const float4*)d_px)[t];
    float4 fy4 = ((const float4*)d_py)[t];

    const float* ib = img + (size_t)b * C * W * W;
    float4 c0, c1, c2;
    samp1(ib, fx4.x, fy4.x, c0.x, c1.x, c2.x);
    samp1(ib, fx4.y, fy4.y, c0.y, c1.y, c2.y);
    samp1(ib, fx4.z, fy4.z, c0.z, c1.z, c2.z);
    samp1(ib, fx4.w, fy4.w, c0.w, c1.w, c2.w);

    size_t orow = ((size_t)(b * C) * W + y) * W;
    int xo = (t & 127) * 4;
    *(float4*)(out + orow + xo)                     = c0;
    *(float4*)(out + orow + (size_t)W * W + xo)     = c1;
    *(float4*)(out + orow + (size_t)2 * W * W + xo) = c2;
}

// ---------------- launch -----------------------------------------------------
extern "C" void kernel_launch(void* const* d_in, const int* in_sizes, int n_in,
                              void* d_out, int out_size) {
    const float* image = (const float*)d_in[0];
    const float* prim  = (const float*)d_in[1];
    if (in_sizes[0] == B * 2 * W * W) {     // defensive input identification
        prim  = (const float*)d_in[0];
        image = (const float*)d_in[1];
    }

    // gaussian weights on host (double, identical to numpy)
    double sigma = 5.0 * 0.15 + 0.35;       // 1.1
    double p0 = exp(-0.5 * (2.0 / sigma) * (2.0 / sigma));
    double p1 = exp(-0.5 * (1.0 / sigma) * (1.0 / sigma));
    double s  = 2.0 * p0 + 2.0 * p1 + 1.0;
    float w0 = (float)(p0 / s), w1 = (float)(p1 / s), w2 = (float)(1.0 / s);

    static bool attr_done = false;
    if (!attr_done) {
        cudaFuncSetAttribute(k_colscan,
                             cudaFuncAttributeMaxDynamicSharedMemorySize,
                             W * 32 * (int)sizeof(float));
        attr_done = true;
    }

    dim3 rg(W / RROWS, B);
    k_rowscan<<<rg, 256>>>(prim, w0, w1, w2);

    dim3 cb(32, NSEG);
    dim3 cg(W / 32, B);
    k_colscan<<<cg, cb, W * 32 * sizeof(float)>>>(prim, w0, w1, w2);

    k_sample<<<(B * W * W / 4 + 255) / 256, 256>>>(image, (float*)d_out);
}